// round 9
// baseline (speedup 1.0000x reference)
#include <cuda_runtime.h>
#include <math.h>

#define S_LEN    4096
#define BATCH    8
#define DMODEL   256
#define NTHREADS 256
#define NWARPS   (NTHREADS / 32)
#define NPAIRS   (S_LEN / 2)             // 2048
#define GROUPS_PER_BATCH (S_LEN / 4)     // 1024 groups of 4 queries
#define GRID     444                     // 3 CTAs/SM * 148

typedef unsigned long long ull;

__device__ int g_ctr[BATCH];

__device__ __forceinline__ float ex2_fast(float x) {
    float r;
    asm("ex2.approx.ftz.f32 %0, %1;" : "=f"(r) : "f"(x));
    return r;
}
__device__ __forceinline__ ull pk2(float a, float b) {
    ull r; asm("mov.b64 %0, {%1, %2};" : "=l"(r) : "f"(a), "f"(b)); return r;
}
__device__ __forceinline__ void upk2(ull v, float& a, float& b) {
    asm("mov.b64 {%0, %1}, %2;" : "=f"(a), "=f"(b) : "l"(v));
}
__device__ __forceinline__ ull fma2(ull a, ull b, ull c) {
    ull r; asm("fma.rn.f32x2 %0, %1, %2, %3;" : "=l"(r) : "l"(a), "l"(b), "l"(c)); return r;
}
__device__ __forceinline__ ull add2(ull a, ull b) {
    ull r; asm("add.rn.f32x2 %0, %1, %2;" : "=l"(r) : "l"(a), "l"(b)); return r;
}

// fully packed fma-pipe exp2 for 2 lanes of a f32x2 (scalar clamps keep the
// masked-key sentinel (-2.2e9 logits) safe; splice adds i<<23 to exponent field)
__device__ __forceinline__ ull exp2_poly2(ull l2,
                                          ull MAGIC2, ull NMAGIC2, ull SGN2,
                                          ull C3, ull C2, ull C1, ull C0, ull ONE2) {
    float a, b; upk2(l2, a, b);
    a = fmaxf(a, -126.0f);
    b = fmaxf(b, -126.0f);
    ull xc = pk2(a, b);
    ull t  = add2(xc, MAGIC2);           // int part captured in mantissa
    ull fi = add2(t, NMAGIC2);           // == t - MAGIC
    ull xf = add2(xc, fi ^ SGN2);        // xc - fi, in [-0.5, 0.5]
    ull p  = fma2(C3, xf, C2);
    p = fma2(p, xf, C1);
    p = fma2(p, xf, C0);
    p = fma2(p, xf, ONE2);
    float tl, th; upk2(t, tl, th);
    float pl, ph; upk2(p, pl, ph);
    int rl = __float_as_int(pl) + (__float_as_int(tl) << 23);
    int rh = __float_as_int(ph) + (__float_as_int(th) << 23);
    return pk2(__int_as_float(rl), __int_as_float(rh));
}

__global__ void dwsa_reset() {
    #pragma unroll
    for (int i = 0; i < BATCH; i++) g_ctr[i] = 0;
}

__global__ __launch_bounds__(NTHREADS, 3)
void dwsa_kernel(const float* __restrict__ x,
                 const float* __restrict__ Wq,
                 const float* __restrict__ Wk,
                 const float* __restrict__ Wv,
                 float* __restrict__ out)
{
    __shared__ float4 kp[NPAIRS];        // {h0,h1,-sz0m,-sz1m}: 32 KB
    __shared__ float  sWv[DMODEL];
    __shared__ float  redD[NWARPS];
    __shared__ float  redM[NWARPS];
    __shared__ int    sHasWork;

    const int tid  = threadIdx.x;
    const int wid  = tid >> 5;
    const int lane = tid & 31;

    // ---- dot(Wq, Wk): 256 threads == DMODEL
    float p = Wq[tid] * Wk[tid];
    #pragma unroll
    for (int o = 16; o; o >>= 1) p += __shfl_xor_sync(0xffffffffu, p, o);
    if (lane == 0) redD[wid] = p;
    sWv[tid] = Wv[tid];
    __syncthreads();
    float dotqk = 0.0f;
    #pragma unroll
    for (int i = 0; i < NWARPS; i++) dotqk += redD[i];

    const float LOG2E = 1.4426950408889634f;
    const float cs  = dotqk * (1.0f / 16.0f) * LOG2E;
    const float nB2 = -0.5f * LOG2E;
    const ull  nB22 = pk2(nB2, nB2);
    const ull  ABSM = 0x7fffffff7fffffffULL;

    // packed poly constants (hoisted)
    const ull MAGIC2  = pk2(12582912.0f, 12582912.0f);
    const ull NMAGIC2 = pk2(-12582912.0f, -12582912.0f);
    const ull SGN2    = 0x8000000080000000ULL;
    const ull C3 = pk2(0.0096181f, 0.0096181f);
    const ull C2 = pk2(0.0557834f, 0.0557834f);
    const ull C1 = pk2(0.2401597f, 0.2401597f);
    const ull C0 = pk2(0.6931472f, 0.6931472f);
    const ull ONE2 = pk2(1.0f, 1.0f);

    // ---- cycle over batches starting at home batch
    for (int i = 0; i < BATCH; ++i) {
        const int b = (blockIdx.x + i) & (BATCH - 1);
        if (tid == 0) sHasWork = (*(volatile int*)&g_ctr[b]) < GROUPS_PER_BATCH;
        __syncthreads();                 // also: everyone done with previous kp
        if (!sHasWork) continue;

        const float4* xb4 = (const float4*)(x + (size_t)b * S_LEN * 2);

        // cooperative table load + hmax
        float hm = 0.0f;
        #pragma unroll
        for (int pi = tid; pi < NPAIRS; pi += NTHREADS) {
            float4 v = xb4[pi];          // {sz0,h0,sz1,h1}
            float n0 = (v.y == 0.0f) ? -3.0e9f : -v.x;
            float n1 = (v.w == 0.0f) ? -3.0e9f : -v.z;
            kp[pi] = make_float4(v.y, v.w, n0, n1);
            hm = fmaxf(hm, fmaxf(fabsf(v.y), fabsf(v.w)));
        }
        #pragma unroll
        for (int o = 16; o; o >>= 1) hm = fmaxf(hm, __shfl_xor_sync(0xffffffffu, hm, o));
        if (lane == 0) redM[wid] = hm;
        __syncthreads();                 // table + redM ready
        float hmax = redM[0];
        #pragma unroll
        for (int j = 1; j < NWARPS; j++) hmax = fmaxf(hmax, redM[j]);

        // ---- warp-autonomous steal loop (no CTA barriers inside)
        for (;;) {
            int g;
            if (lane == 0) g = atomicAdd(&g_ctr[b], 1);
            g = __shfl_sync(0xffffffffu, g, 0);
            if (g >= GROUPS_PER_BATCH) break;

            // 4 consecutive queries; broadcast LDG of their (sz, h)
            const float4* xq4 = (const float4*)((const float2*)xb4 + g * 4);
            const float4 A = xq4[0];     // {z0,h0,z1,h1}
            const float4 Bq = xq4[1];    // {z2,h2,z3,h3}

            ull aq2[4], nm2[4], zq2[4];
            {
                const float zz[4] = {A.x, A.z, Bq.x, Bq.z};
                const float hh[4] = {A.y, A.w, Bq.y, Bq.w};
                #pragma unroll
                for (int q = 0; q < 4; q++) {
                    float aq = cs * hh[q];
                    float nm = -fabsf(aq) * hmax;
                    aq2[q] = pk2(aq, aq);
                    nm2[q] = pk2(nm, nm);
                    zq2[q] = pk2(zz[q], zz[q]);
                }
            }

            ull se[4] = {0, 0, 0, 0};
            ull sw[4] = {0, 0, 0, 0};

            // lane's keys: pairs lane + 32k, k = 0..63; one LDS.128 serves 4 queries
            #pragma unroll 2
            for (int k = 0; k < 64; ++k) {
                float4 v = kp[k * 32 + lane];
                ull h2 = pk2(v.x, v.y);
                ull n2 = pk2(v.z, v.w);
                #pragma unroll
                for (int q = 0; q < 4; q++) {
                    ull d2 = add2(zq2[q], n2) & ABSM;
                    ull l2 = fma2(nB22, d2, fma2(aq2[q], h2, nm2[q]));
                    ull e2;
                    if (q < 3) {
                        float l0, l1; upk2(l2, l0, l1);
                        e2 = pk2(ex2_fast(l0), ex2_fast(l1));
                    } else {
                        e2 = exp2_poly2(l2, MAGIC2, NMAGIC2, SGN2, C3, C2, C1, C0, ONE2);
                    }
                    se[q] = add2(se[q], e2);
                    sw[q] = fma2(e2, h2, sw[q]);
                }
            }

            // reduce + write, one row per query
            #pragma unroll
            for (int q = 0; q < 4; q++) {
                float s0, s1; upk2(se[q], s0, s1);
                float w0, w1; upk2(sw[q], w0, w1);
                float seS = s0 + s1;
                float swS = w0 + w1;
                #pragma unroll
                for (int o = 16; o; o >>= 1) {
                    seS += __shfl_xor_sync(0xffffffffu, seS, o);
                    swS += __shfl_xor_sync(0xffffffffu, swS, o);
                }
                const float wv = swS / seS;
                float4* orow = (float4*)(out + ((size_t)b * S_LEN + g * 4 + q) * DMODEL);
                const float4* wv4 = (const float4*)sWv;
                float4 a0 = wv4[lane];
                a0.x *= wv; a0.y *= wv; a0.z *= wv; a0.w *= wv;
                orow[lane] = a0;
                float4 a1 = wv4[lane + 32];
                a1.x *= wv; a1.y *= wv; a1.z *= wv; a1.w *= wv;
                orow[lane + 32] = a1;
            }
        }
    }
}

extern "C" void kernel_launch(void* const* d_in, const int* in_sizes, int n_in,
                              void* d_out, int out_size)
{
    const float* x  = (const float*)d_in[0];
    const float* Wq = (const float*)d_in[1];
    const float* Wk = (const float*)d_in[2];
    const float* Wv = (const float*)d_in[3];
    float* out = (float*)d_out;

    dwsa_reset<<<1, 1>>>();
    dwsa_kernel<<<GRID, NTHREADS>>>(x, Wq, Wk, Wv, out);
}

// round 10
// speedup vs baseline: 1.1545x; 1.1545x over previous
#include <cuda_runtime.h>
#include <math.h>

#define S_LEN    4096
#define BATCH    8
#define DMODEL   256
#define NTHREADS 256
#define NWARPS   (NTHREADS / 32)
#define NPAIRS   (S_LEN / 2)             // 2048
#define GROUPS_PER_BATCH (S_LEN / 4)     // 1024 groups of 4 queries
#define GRID     444

typedef unsigned long long ull;

__device__ int g_ctr[BATCH];

__device__ __forceinline__ float ex2_fast(float x) {
    float r;
    asm("ex2.approx.ftz.f32 %0, %1;" : "=f"(r) : "f"(x));
    return r;
}
__device__ __forceinline__ ull pk2(float a, float b) {
    ull r; asm("mov.b64 %0, {%1, %2};" : "=l"(r) : "f"(a), "f"(b)); return r;
}
__device__ __forceinline__ void upk2(ull v, float& a, float& b) {
    asm("mov.b64 {%0, %1}, %2;" : "=f"(a), "=f"(b) : "l"(v));
}
__device__ __forceinline__ ull fma2(ull a, ull b, ull c) {
    ull r; asm("fma.rn.f32x2 %0, %1, %2, %3;" : "=l"(r) : "l"(a), "l"(b), "l"(c)); return r;
}
__device__ __forceinline__ ull add2(ull a, ull b) {
    ull r; asm("add.rn.f32x2 %0, %1, %2;" : "=l"(r) : "l"(a), "l"(b)); return r;
}

// packed fma-pipe exp2 (clamped; handles the -2.2e9 sentinel safely)
__device__ __forceinline__ ull exp2_poly2(ull l2) {
    const float MAGIC = 12582912.0f;   // 1.5 * 2^23
    float a, b; upk2(l2, a, b);
    a = fmaxf(a, -126.0f);
    b = fmaxf(b, -126.0f);
    float ta = a + MAGIC, tb = b + MAGIC;
    float xa = a - (ta - MAGIC);
    float xb = b - (tb - MAGIC);
    ull xf = pk2(xa, xb);
    ull p  = fma2(pk2(0.0096181f, 0.0096181f), xf, pk2(0.0557834f, 0.0557834f));
    p = fma2(p, xf, pk2(0.2401597f, 0.2401597f));
    p = fma2(p, xf, pk2(0.6931472f, 0.6931472f));
    p = fma2(p, xf, pk2(1.0f, 1.0f));
    float pl, ph; upk2(p, pl, ph);
    int rl = __float_as_int(pl) + (__float_as_int(ta) << 23);
    int rh = __float_as_int(ph) + (__float_as_int(tb) << 23);
    return pk2(__int_as_float(rl), __int_as_float(rh));
}

__global__ void dwsa_reset() {
    #pragma unroll
    for (int i = 0; i < BATCH; i++) g_ctr[i] = 0;
}

__global__ __launch_bounds__(NTHREADS, 3)
void dwsa_kernel(const float* __restrict__ x,
                 const float* __restrict__ Wq,
                 const float* __restrict__ Wk,
                 const float* __restrict__ Wv,
                 float* __restrict__ out)
{
    __shared__ float4 kp[NPAIRS];        // {h0, h1, nr0, nr1}, nr = -B2*sz (sentineled)
    __shared__ float  sWv[DMODEL];
    __shared__ float  redD[NWARPS];
    __shared__ int    sHasWork;

    const int tid  = threadIdx.x;
    const int wid  = tid >> 5;
    const int lane = tid & 31;

    // ---- dot(Wq, Wk)
    float p = Wq[tid] * Wk[tid];
    #pragma unroll
    for (int o = 16; o; o >>= 1) p += __shfl_xor_sync(0xffffffffu, p, o);
    if (lane == 0) redD[wid] = p;
    sWv[tid] = Wv[tid];
    __syncthreads();
    float dotqk = 0.0f;
    #pragma unroll
    for (int i = 0; i < NWARPS; i++) dotqk += redD[i];

    const float LOG2E = 1.4426950408889634f;
    const float cs = dotqk * (1.0f / 16.0f) * LOG2E;   // log2-domain q.k scale
    const float B2 = 0.5f * LOG2E;                     // lambda in log2 domain
    const ull  SGN2 = 0x8000000080000000ULL;           // OR -> -|x| per lane

    for (int i = 0; i < BATCH; ++i) {
        const int b = (blockIdx.x + i) & (BATCH - 1);
        if (tid == 0) sHasWork = (*(volatile int*)&g_ctr[b]) < GROUPS_PER_BATCH;
        __syncthreads();                 // also: all warps done with previous kp
        if (!sHasWork) continue;

        const float4* xb4 = (const float4*)(x + (size_t)b * S_LEN * 2);

        // table load: {sz0,h0,sz1,h1} -> {h0, h1, -B2*sz0m, -B2*sz1m}
        #pragma unroll
        for (int pi = tid; pi < NPAIRS; pi += NTHREADS) {
            float4 v = xb4[pi];
            float nr0 = (v.y == 0.0f) ? -2.2e9f : -B2 * v.x;
            float nr1 = (v.w == 0.0f) ? -2.2e9f : -B2 * v.z;
            kp[pi] = make_float4(v.y, v.w, nr0, nr1);
        }
        __syncthreads();

        // ---- warp-autonomous steal loop
        for (;;) {
            int g;
            if (lane == 0) g = atomicAdd(&g_ctr[b], 1);
            g = __shfl_sync(0xffffffffu, g, 0);
            if (g >= GROUPS_PER_BATCH) break;

            const float4* xq4 = (const float4*)((const float2*)xb4 + g * 4);
            const float4 A  = xq4[0];    // {z0,h0,z1,h1}
            const float4 Bq = xq4[1];    // {z2,h2,z3,h3}

            ull aq2[4], bz2[4];
            {
                const float zz[4] = {A.x, A.z, Bq.x, Bq.z};
                const float hh[4] = {A.y, A.w, Bq.y, Bq.w};
                #pragma unroll
                for (int q = 0; q < 4; q++) {
                    float aq = cs * hh[q];
                    float bz = B2 * zz[q];
                    aq2[q] = pk2(aq, aq);
                    bz2[q] = pk2(bz, bz);
                }
            }

            ull se[4] = {0, 0, 0, 0};
            ull sw[4] = {0, 0, 0, 0};

            // lane's pairs: lane + 32k; body: l = aq*h - |B2*zq - B2*sz|
            // q==3 on odd k uses the fma-pipe poly (f = 1/8 MUFU offload)
            #pragma unroll 2
            for (int k = 0; k < 64; ++k) {
                float4 v = kp[k * 32 + lane];
                ull h2 = pk2(v.x, v.y);
                ull n2 = pk2(v.z, v.w);
                #pragma unroll
                for (int q = 0; q < 4; q++) {
                    ull nd2 = add2(bz2[q], n2) | SGN2;          // -|B2(zq - sz)|
                    ull l2  = fma2(aq2[q], h2, nd2);
                    ull e2;
                    if (q == 3 && (k & 1)) {
                        e2 = exp2_poly2(l2);
                    } else {
                        float l0, l1; upk2(l2, l0, l1);
                        e2 = pk2(ex2_fast(l0), ex2_fast(l1));
                    }
                    se[q] = add2(se[q], e2);
                    sw[q] = fma2(e2, h2, sw[q]);
                }
            }

            // reduce + write, one row per query
            #pragma unroll
            for (int q = 0; q < 4; q++) {
                float s0, s1; upk2(se[q], s0, s1);
                float w0, w1; upk2(sw[q], w0, w1);
                float seS = s0 + s1;
                float swS = w0 + w1;
                #pragma unroll
                for (int o = 16; o; o >>= 1) {
                    seS += __shfl_xor_sync(0xffffffffu, seS, o);
                    swS += __shfl_xor_sync(0xffffffffu, swS, o);
                }
                const float wv = swS / seS;
                float4* orow = (float4*)(out + ((size_t)b * S_LEN + g * 4 + q) * DMODEL);
                const float4* wv4 = (const float4*)sWv;
                float4 a0 = wv4[lane];
                a0.x *= wv; a0.y *= wv; a0.z *= wv; a0.w *= wv;
                orow[lane] = a0;
                float4 a1 = wv4[lane + 32];
                a1.x *= wv; a1.y *= wv; a1.z *= wv; a1.w *= wv;
                orow[lane + 32] = a1;
            }
        }
    }
}

extern "C" void kernel_launch(void* const* d_in, const int* in_sizes, int n_in,
                              void* d_out, int out_size)
{
    const float* x  = (const float*)d_in[0];
    const float* Wq = (const float*)d_in[1];
    const float* Wk = (const float*)d_in[2];
    const float* Wv = (const float*)d_in[3];
    float* out = (float*)d_out;

    dwsa_reset<<<1, 1>>>();
    dwsa_kernel<<<GRID, NTHREADS>>>(x, Wq, Wk, Wv, out);
}